// round 1
// baseline (speedup 1.0000x reference)
#include <cuda_runtime.h>
#include <math.h>

#define N_NODES 1024
#define H 128
#define BI 8            // query rows per block
#define BJ 32           // key rows per tile
#define THREADS 256
#define NTILES (N_NODES / BJ)
#define HP (H + 1)      // padded stride for conflict-free LDS

// Scratch (static device globals — no allocation)
__device__ float g_q[N_NODES * H];
__device__ float g_k[N_NODES * H];
__device__ float g_v[N_NODES * H];
__device__ float g_u[N_NODES * H];   // x @ We1
__device__ float g_ub[N_NODES * H];  // u + be1
__device__ float g_w[H];             // We2 @ Wc
__device__ float g_c;                // be2 @ Wc + bc

// ---------------------------------------------------------------------------
// Kernel 0: fold edge-MLP tail: w[m] = sum_o We2[m][o]*Wc[o];  c = be2@Wc + bc
// ---------------------------------------------------------------------------
__global__ void prep0_kernel(const float* __restrict__ We2,
                             const float* __restrict__ be2,
                             const float* __restrict__ Wc,
                             const float* __restrict__ bc)
{
    int m = threadIdx.x;  // 0..127
    float acc = 0.f;
#pragma unroll 8
    for (int o = 0; o < H; ++o)
        acc = fmaf(We2[m * H + o], Wc[o], acc);
    g_w[m] = acc;

    __shared__ float part[H];
    part[m] = be2[m] * Wc[m];
    __syncthreads();
    for (int s = 64; s > 0; s >>= 1) {
        if (m < s) part[m] += part[m + s];
        __syncthreads();
    }
    if (m == 0) g_c = part[0] + bc[0];
}

// ---------------------------------------------------------------------------
// Kernel 1: q,k,v = h@W + b  (fused, 8 rows/block) and u = x@We1, ub = u+be1
// ---------------------------------------------------------------------------
__global__ __launch_bounds__(THREADS)
void prep1_kernel(const float* __restrict__ h, const float* __restrict__ x,
                  const float* __restrict__ Wq, const float* __restrict__ bq,
                  const float* __restrict__ Wk, const float* __restrict__ bk,
                  const float* __restrict__ Wv, const float* __restrict__ bv,
                  const float* __restrict__ We1, const float* __restrict__ be1)
{
    __shared__ float hs[8][H];
    __shared__ float xs2[8][2];
    int t = threadIdx.x;
    int r0 = blockIdx.x * 8;

    for (int idx = t; idx < 8 * H; idx += THREADS)
        hs[idx >> 7][idx & 127] = h[r0 * H + idx];
    if (t < 16) xs2[t >> 1][t & 1] = x[r0 * 2 + t];
    __syncthreads();

    int o = t & 127;
    int g = t >> 7;  // 0/1 -> rows g*4 .. g*4+3

    float aq[4], ak[4], av[4];
    float bqv = bq[o], bkv = bk[o], bvv = bv[o];
#pragma unroll
    for (int r = 0; r < 4; ++r) { aq[r] = bqv; ak[r] = bkv; av[r] = bvv; }

#pragma unroll 4
    for (int m = 0; m < H; ++m) {
        float wq = Wq[m * H + o];
        float wk = Wk[m * H + o];
        float wv = Wv[m * H + o];
#pragma unroll
        for (int r = 0; r < 4; ++r) {
            float hm = hs[g * 4 + r][m];
            aq[r] = fmaf(hm, wq, aq[r]);
            ak[r] = fmaf(hm, wk, ak[r]);
            av[r] = fmaf(hm, wv, av[r]);
        }
    }
#pragma unroll
    for (int r = 0; r < 4; ++r) {
        int row = r0 + g * 4 + r;
        g_q[row * H + o] = aq[r];
        g_k[row * H + o] = ak[r];
        g_v[row * H + o] = av[r];
    }

    float w0 = We1[o], w1 = We1[H + o], b1 = be1[o];
#pragma unroll
    for (int r = 0; r < 4; ++r) {
        int row = r0 + g * 4 + r;
        float u = fmaf(xs2[g * 4 + r][0], w0, xs2[g * 4 + r][1] * w1);
        g_u[row * H + o] = u;
        g_ub[row * H + o] = u + b1;
    }
}

// ---------------------------------------------------------------------------
// Kernel 2: fused attention + equivariant coordinate update
// Block = 8 query rows. Warp wi owns query row i0+wi (row-private p storage).
// ---------------------------------------------------------------------------
__global__ __launch_bounds__(THREADS)
void main_kernel(const float* __restrict__ h, const float* __restrict__ x,
                 float* __restrict__ out_h, float* __restrict__ out_x)
{
    extern __shared__ float smem[];
    // layout
    float* p_base  = smem;                       // BI * N_NODES
    float* qs_base = p_base  + BI * N_NODES;     // BI * H
    float* ub_base = qs_base + BI * H;           // BI * H
    float* tA_base = ub_base + BI * H;           // BJ * HP  (k / u tile)
    float* tB_base = tA_base + BJ * HP;          // BJ * HP  (v tile)
    float* ws      = tB_base + BJ * HP;          // H
    float* xs      = ws + H;                     // BJ * 2
    float* xi      = xs + BJ * 2;                // BI * 2

    float (*p)[N_NODES] = (float(*)[N_NODES])p_base;
    float (*qs)[H]      = (float(*)[H])qs_base;
    float (*ubs)[H]     = (float(*)[H])ub_base;
    float (*tA)[HP]     = (float(*)[HP])tA_base;
    float (*tB)[HP]     = (float(*)[HP])tB_base;

    int t = threadIdx.x;
    int i0 = blockIdx.x * BI;
    int wi = t >> 5;     // warp index == local query row
    int lane = t & 31;

    for (int idx = t; idx < BI * H; idx += THREADS) {
        int ii = idx >> 7, mm = idx & 127;
        qs[ii][mm]  = g_q[(i0 + ii) * H + mm];
        ubs[ii][mm] = g_ub[(i0 + ii) * H + mm];
    }
    if (t < H) ws[t] = g_w[t];
    if (t < BI * 2) xi[t] = x[i0 * 2 + t];
    __syncthreads();

    const float scale = rsqrtf((float)H);

    // ---------------- Pass 1: scores S = q k^T * scale --------------------
    for (int jt = 0; jt < NTILES; ++jt) {
        int j0 = jt * BJ;
        for (int idx = t; idx < BJ * H; idx += THREADS) {
            int jj = idx >> 7, mm = idx & 127;
            tA[jj][mm] = g_k[(j0 + jj) * H + mm];
        }
        __syncthreads();
        float acc = 0.f;
#pragma unroll 16
        for (int m = 0; m < H; ++m)
            acc = fmaf(qs[wi][m], tA[lane][m], acc);
        p[wi][j0 + lane] = acc * scale;
        __syncthreads();
    }

    // ---------------- Softmax (row-private per warp) ----------------------
    {
        float mx = -1e30f;
        for (int j = lane; j < N_NODES; j += 32) mx = fmaxf(mx, p[wi][j]);
#pragma unroll
        for (int s = 16; s > 0; s >>= 1)
            mx = fmaxf(mx, __shfl_xor_sync(0xffffffffu, mx, s));
        float sum = 0.f;
        for (int j = lane; j < N_NODES; j += 32) {
            float e = __expf(p[wi][j] - mx);
            p[wi][j] = e;
            sum += e;
        }
#pragma unroll
        for (int s = 16; s > 0; s >>= 1)
            sum += __shfl_xor_sync(0xffffffffu, sum, s);
        float inv = 1.f / sum;
        for (int j = lane; j < N_NODES; j += 32) p[wi][j] *= inv;
    }
    __syncthreads();

    // ---------------- Pass 2: agg_h and delta_x ---------------------------
    float accv0 = 0.f, accv1 = 0.f, accv2 = 0.f, accv3 = 0.f;
    float dxx = 0.f, dxy = 0.f;
    const float cc  = g_c;
    const float xi0 = xi[wi * 2 + 0];
    const float xi1 = xi[wi * 2 + 1];

    for (int jt = 0; jt < NTILES; ++jt) {
        int j0 = jt * BJ;
        for (int idx = t; idx < BJ * H; idx += THREADS) {
            int jj = idx >> 7, mm = idx & 127;
            tA[jj][mm] = g_u[(j0 + jj) * H + mm];
            tB[jj][mm] = g_v[(j0 + jj) * H + mm];
        }
        if (t < BJ * 2) xs[t] = x[j0 * 2 + t];
        __syncthreads();

        // phase A: gate for pair (i0+wi, j0+lane), accumulate delta_x
        {
            float g = 0.f;
#pragma unroll 16
            for (int m = 0; m < H; ++m) {
                float a = ubs[wi][m] - tA[lane][m];
                g = fmaf(fmaxf(a, 0.f), ws[m], g);
            }
            float pij = p[wi][j0 + lane];
            float pg = pij * (g + cc);
            dxx = fmaf(pg, xi0 - xs[lane * 2 + 0], dxx);
            dxy = fmaf(pg, xi1 - xs[lane * 2 + 1], dxy);
        }

        // phase B: agg_h; thread (wi,lane) owns cols lane + 32r
        {
#pragma unroll
            for (int jj = 0; jj < BJ; ++jj) {
                float pj = p[wi][j0 + jj];
                accv0 = fmaf(pj, tB[jj][lane +  0], accv0);
                accv1 = fmaf(pj, tB[jj][lane + 32], accv1);
                accv2 = fmaf(pj, tB[jj][lane + 64], accv2);
                accv3 = fmaf(pj, tB[jj][lane + 96], accv3);
            }
        }
        __syncthreads();
    }

    // ---------------- Epilogue --------------------------------------------
    int gi = i0 + wi;
    out_h[gi * H + lane +  0] = h[gi * H + lane +  0] + accv0;
    out_h[gi * H + lane + 32] = h[gi * H + lane + 32] + accv1;
    out_h[gi * H + lane + 64] = h[gi * H + lane + 64] + accv2;
    out_h[gi * H + lane + 96] = h[gi * H + lane + 96] + accv3;

#pragma unroll
    for (int s = 16; s > 0; s >>= 1) {
        dxx += __shfl_xor_sync(0xffffffffu, dxx, s);
        dxy += __shfl_xor_sync(0xffffffffu, dxy, s);
    }
    if (lane == 0) {
        out_x[gi * 2 + 0] = x[gi * 2 + 0] + dxx;
        out_x[gi * 2 + 1] = x[gi * 2 + 1] + dxy;
    }
}

// ---------------------------------------------------------------------------
extern "C" void kernel_launch(void* const* d_in, const int* in_sizes, int n_in,
                              void* d_out, int out_size)
{
    const float* h   = (const float*)d_in[0];
    const float* x   = (const float*)d_in[1];
    // d_in[2] = batch (int64, unused — single batch, reference ignores it)
    const float* Wq  = (const float*)d_in[3];
    const float* bq  = (const float*)d_in[4];
    const float* Wk  = (const float*)d_in[5];
    const float* bk  = (const float*)d_in[6];
    const float* Wv  = (const float*)d_in[7];
    const float* bv  = (const float*)d_in[8];
    const float* We1 = (const float*)d_in[9];
    const float* be1 = (const float*)d_in[10];
    const float* We2 = (const float*)d_in[11];
    const float* be2 = (const float*)d_in[12];
    const float* Wc  = (const float*)d_in[13];
    const float* bc  = (const float*)d_in[14];

    float* out   = (float*)d_out;
    float* out_h = out;                     // [N, H]
    float* out_x = out + N_NODES * H;       // [N, 2]

    // dynamic smem for main kernel
    size_t smem_bytes = (size_t)(BI * N_NODES + 2 * BI * H + 2 * BJ * HP
                                 + H + BJ * 2 + BI * 2) * sizeof(float);
    cudaFuncSetAttribute(main_kernel,
                         cudaFuncAttributeMaxDynamicSharedMemorySize,
                         (int)smem_bytes);

    prep0_kernel<<<1, H>>>(We2, be2, Wc, bc);
    prep1_kernel<<<N_NODES / 8, THREADS>>>(h, x, Wq, bq, Wk, bk, Wv, bv, We1, be1);
    main_kernel<<<N_NODES / BI, THREADS, smem_bytes>>>(h, x, out_h, out_x);
}

// round 2
// speedup vs baseline: 1.7687x; 1.7687x over previous
#include <cuda_runtime.h>
#include <math.h>

#define N_NODES 1024
#define H 128
#define BI 8
#define THREADS 256

typedef unsigned long long u64;
#define ABSM 0x7FFFFFFF7FFFFFFFULL

// ---------------- f32x2 packed helpers ----------------
__device__ __forceinline__ u64 f2add(u64 a, u64 b) {
    u64 r; asm("add.rn.f32x2 %0,%1,%2;" : "=l"(r) : "l"(a), "l"(b)); return r;
}
__device__ __forceinline__ void f2fma(u64& d, u64 a, u64 b) {
    asm("fma.rn.f32x2 %0,%1,%2,%0;" : "+l"(d) : "l"(a), "l"(b));
}
__device__ __forceinline__ float2 f2unpack(u64 v) {
    float2 f; asm("mov.b64 {%0,%1},%2;" : "=f"(f.x), "=f"(f.y) : "l"(v)); return f;
}
__device__ __forceinline__ u64 f2pack(float a, float b) {
    u64 r; asm("mov.b64 %0,{%1,%2};" : "=l"(r) : "f"(a), "f"(b)); return r;
}

// ---------------- device scratch ----------------
__device__ float g_q[N_NODES * H];      // q * 1/sqrt(H)
__device__ float g_k[N_NODES * H];
__device__ float g_v[N_NODES * H];
__device__ float g_alpha[N_NODES * H];  // 0.5*w*(u+be1)
__device__ float g_beta[N_NODES * H];   // -0.5*w*u
__device__ float g_A[N_NODES];          // sum_m alpha
__device__ float g_B[N_NODES];          // sum_m beta
__device__ float g_w[H];                // We2 @ Wc
__device__ float g_sig[H];              // sign(w) as +-1.0f
__device__ float g_c;                   // be2 @ Wc + bc

// ---------------------------------------------------------------------------
// prep_w: w[m] = We2[m,:] @ Wc ; sigma ; c = be2@Wc + bc   (1 block, 256 thr)
// ---------------------------------------------------------------------------
__global__ __launch_bounds__(256) void prep_w_kernel(const float* __restrict__ We2,
                                                     const float* __restrict__ be2,
                                                     const float* __restrict__ Wc,
                                                     const float* __restrict__ bc)
{
    int t = threadIdx.x;
    int m = t >> 1, half = t & 1;
    const float* row = We2 + m * H + half * 64;
    const float* wc  = Wc + half * 64;
    float acc = 0.f;
#pragma unroll 16
    for (int o = 0; o < 64; ++o) acc = fmaf(row[o], wc[o], acc);
    acc += __shfl_xor_sync(0xffffffffu, acc, 1);
    if (!half) {
        g_w[m] = acc;
        g_sig[m] = (acc >= 0.f) ? 1.0f : -1.0f;
    }
    __shared__ float part[128];
    if (t < 128) part[t] = be2[t] * Wc[t];
    __syncthreads();
    for (int s = 64; s > 0; s >>= 1) {
        if (t < s) part[t] += part[t + s];
        __syncthreads();
    }
    if (t == 0) g_c = part[0] + bc[0];
}

// ---------------------------------------------------------------------------
// prep_node: q (scaled),k,v ; alpha,beta,A,B   (128 blocks x 256 thr)
// ---------------------------------------------------------------------------
__global__ __launch_bounds__(THREADS)
void prep_node_kernel(const float* __restrict__ h, const float* __restrict__ x,
                      const float* __restrict__ Wq, const float* __restrict__ bq,
                      const float* __restrict__ Wk, const float* __restrict__ bk,
                      const float* __restrict__ Wv, const float* __restrict__ bv,
                      const float* __restrict__ We1, const float* __restrict__ be1)
{
    __shared__ float hs[8 * H];
    __shared__ float xs2[8][2];
    __shared__ float ws[H];
    __shared__ float wpart[8][4][2];
    int t = threadIdx.x;
    int r0 = blockIdx.x * 8;

    for (int idx = t; idx < 8 * H; idx += THREADS) hs[idx] = h[r0 * H + idx];
    if (t < 16) xs2[t >> 1][t & 1] = x[r0 * 2 + t];
    if (t < H) ws[t] = g_w[t];
    __syncthreads();

    int o = t & 127;
    int g = t >> 7;

    const float SCALE = 0.08838834764831845f;  // 1/sqrt(128)

    float aq[4], ak[4], av[4];
    float bqv = bq[o], bkv = bk[o], bvv = bv[o];
#pragma unroll
    for (int r = 0; r < 4; ++r) { aq[r] = bqv; ak[r] = bkv; av[r] = bvv; }

#pragma unroll 4
    for (int m = 0; m < H; ++m) {
        float wq = Wq[m * H + o];
        float wk = Wk[m * H + o];
        float wv = Wv[m * H + o];
#pragma unroll
        for (int r = 0; r < 4; ++r) {
            float hm = hs[(g * 4 + r) * H + m];
            aq[r] = fmaf(hm, wq, aq[r]);
            ak[r] = fmaf(hm, wk, ak[r]);
            av[r] = fmaf(hm, wv, av[r]);
        }
    }
#pragma unroll
    for (int r = 0; r < 4; ++r) {
        int row = r0 + g * 4 + r;
        g_q[row * H + o] = aq[r] * SCALE;
        g_k[row * H + o] = ak[r];
        g_v[row * H + o] = av[r];
    }

    float w0 = We1[o], w1 = We1[H + o], b1 = be1[o], wo = ws[o];
    float sA[4], sB[4];
#pragma unroll
    for (int r = 0; r < 4; ++r) {
        int row = r0 + g * 4 + r;
        float u  = fmaf(xs2[g * 4 + r][0], w0, xs2[g * 4 + r][1] * w1);
        float ub = u + b1;
        float al = 0.5f * wo * ub;
        float be = -0.5f * wo * u;
        g_alpha[row * H + o] = al;
        g_beta[row * H + o]  = be;
        sA[r] = al; sB[r] = be;
    }
#pragma unroll
    for (int s = 16; s > 0; s >>= 1) {
#pragma unroll
        for (int r = 0; r < 4; ++r) {
            sA[r] += __shfl_xor_sync(0xffffffffu, sA[r], s);
            sB[r] += __shfl_xor_sync(0xffffffffu, sB[r], s);
        }
    }
    int w = t >> 5, lane = t & 31;
    if (lane == 0) {
#pragma unroll
        for (int r = 0; r < 4; ++r) { wpart[w][r][0] = sA[r]; wpart[w][r][1] = sB[r]; }
    }
    __syncthreads();
    if (t < 8) {
        int gg = t >> 2, rr = t & 3;
        float A = 0.f, B = 0.f;
#pragma unroll
        for (int ww = 0; ww < 4; ++ww) {
            A += wpart[4 * gg + ww][rr][0];
            B += wpart[4 * gg + ww][rr][1];
        }
        int row = r0 + gg * 4 + rr;
        g_A[row] = A;
        g_B[row] = B;
    }
}

// ---------------------------------------------------------------------------
// main kernel: fused attention + gate + coordinate update (128 blocks x 256)
// ---------------------------------------------------------------------------
// smem float offsets
#define OFF_P    0            // 8*1024
#define OFF_AS   8192         // 8*128
#define OFF_QS   9216         // 8*128
#define OFF_SS   10240        // 128
#define OFF_DXR  10368        // 64
#define OFF_TILE 10432
#define TILE_KT_ROWS 132      // padded row stride (16B-aligned, conflict-free)
#define OFF_VT   (OFF_TILE + 8448)   // 64*132
#define OFF_XS   (OFF_TILE + 16896)  // 64*2
#define OFF_BT   (OFF_TILE + 17024)  // 64
#define SMEM_FLOATS (OFF_TILE + 17088)

__global__ __launch_bounds__(THREADS)
void main_kernel(const float* __restrict__ h, const float* __restrict__ x,
                 float* __restrict__ out_h, float* __restrict__ out_x)
{
    extern __shared__ float sm[];
    float* P  = sm + OFF_P;
    float* AS = sm + OFF_AS;
    float* QS = sm + OFF_QS;
    float* SS = sm + OFF_SS;
    float* DXR = sm + OFF_DXR;
    float* TL = sm + OFF_TILE;

    int t = threadIdx.x;
    int i0 = blockIdx.x * BI;

    for (int idx = t; idx < BI * H; idx += THREADS) {
        int ii = idx >> 7, mm = idx & 127;
        QS[idx] = g_q[(i0 + ii) * H + mm];
        AS[idx] = g_alpha[(i0 + ii) * H + mm];
    }
    if (t < H) SS[t] = g_sig[t];
    __syncthreads();

    // ================= Pass 1: scores =================
    {
        int ig = t >> 7;         // 0..1 -> i rows 4ig..4ig+3 (warp-uniform)
        int jl = t & 127;
        for (int jt = 0; jt < 8; ++jt) {
            int j0 = jt * 128;
            for (int idx = t; idx < 4096; idx += THREADS) {
                int row = idx >> 5, c4 = idx & 31;
                *(float4*)&TL[row * TILE_KT_ROWS + 4 * c4] =
                    *(const float4*)&g_k[(j0 + row) * H + 4 * c4];
            }
            __syncthreads();
            u64 acc[4] = {0ull, 0ull, 0ull, 0ull};
            const ulonglong2* kr = (const ulonglong2*)&TL[jl * TILE_KT_ROWS];
#pragma unroll 8
            for (int mc = 0; mc < 32; ++mc) {
                ulonglong2 k2 = kr[mc];
#pragma unroll
                for (int r = 0; r < 4; ++r) {
                    ulonglong2 q2 = ((const ulonglong2*)&QS[(4 * ig + r) * H])[mc];
                    f2fma(acc[r], q2.x, k2.x);
                    f2fma(acc[r], q2.y, k2.y);
                }
            }
#pragma unroll
            for (int r = 0; r < 4; ++r) {
                float2 f = f2unpack(acc[r]);
                P[(4 * ig + r) * N_NODES + j0 + jl] = f.x + f.y;
            }
            __syncthreads();
        }
    }

    // ================= Softmax (warp wi owns row wi) =================
    {
        int wi = t >> 5, lane = t & 31;
        float* prow = &P[wi * N_NODES];
        float mx = -1e30f;
        for (int j = lane; j < N_NODES; j += 32) mx = fmaxf(mx, prow[j]);
#pragma unroll
        for (int s = 16; s > 0; s >>= 1)
            mx = fmaxf(mx, __shfl_xor_sync(0xffffffffu, mx, s));
        float sum = 0.f;
        for (int j = lane; j < N_NODES; j += 32) {
            float e = __expf(prow[j] - mx);
            prow[j] = e;
            sum += e;
        }
#pragma unroll
        for (int s = 16; s > 0; s >>= 1)
            sum += __shfl_xor_sync(0xffffffffu, sum, s);
        float inv = 1.f / sum;
        for (int j = lane; j < N_NODES; j += 32) prow[j] *= inv;
    }
    __syncthreads();

    // ================= Pass 2: gate + delta_x + agg_h =================
    int igA = t >> 6;   // 0..3 -> i rows 2igA, 2igA+1 (warp-uniform)
    int jlA = t & 63;
    int iB = t >> 5;    // AV: warp = i row
    int c4 = t & 31;    // AV: cols 4c4..4c4+3

    float dxx0 = 0.f, dxy0 = 0.f, dxx1 = 0.f, dxy1 = 0.f;
    u64 av0 = 0ull, av1 = 0ull;

    float cc = g_c;
    float ccA0, ccA1, xix0, xiy0, xix1, xiy1;
    {
        int gi0 = i0 + 2 * igA, gi1 = gi0 + 1;
        ccA0 = cc + g_A[gi0]; ccA1 = cc + g_A[gi1];
        xix0 = x[gi0 * 2]; xiy0 = x[gi0 * 2 + 1];
        xix1 = x[gi1 * 2]; xiy1 = x[gi1 * 2 + 1];
    }

    for (int jt = 0; jt < 16; ++jt) {
        int j0 = jt * 64;
        for (int idx = t; idx < 2048; idx += THREADS) {
            int row = idx >> 5, cb = idx & 31;
            *(float4*)&TL[row * TILE_KT_ROWS + 4 * cb] =
                *(const float4*)&g_beta[(j0 + row) * H + 4 * cb];
            *(float4*)&sm[OFF_VT + row * TILE_KT_ROWS + 4 * cb] =
                *(const float4*)&g_v[(j0 + row) * H + 4 * cb];
        }
        if (t < 64) {
            sm[OFF_XS + 2 * t]     = x[(j0 + t) * 2];
            sm[OFF_XS + 2 * t + 1] = x[(j0 + t) * 2 + 1];
            sm[OFF_BT + t]         = g_B[j0 + t];
        }
        __syncthreads();

        // ---- phase A: gate + delta_x ----
        {
            u64 ga0 = 0ull, ga1 = 0ull;
            const ulonglong2* br = (const ulonglong2*)&TL[jlA * TILE_KT_ROWS];
            const ulonglong2* srp = (const ulonglong2*)SS;
            const ulonglong2* a0p = (const ulonglong2*)&AS[(2 * igA) * H];
            const ulonglong2* a1p = (const ulonglong2*)&AS[(2 * igA + 1) * H];
#pragma unroll 8
            for (int mc = 0; mc < 32; ++mc) {
                ulonglong2 b2 = br[mc];
                ulonglong2 s2 = srp[mc];
                ulonglong2 a0 = a0p[mc];
                ulonglong2 a1 = a1p[mc];
                u64 gx;
                gx = f2add(a0.x, b2.x) & ABSM; f2fma(ga0, gx, s2.x);
                gx = f2add(a0.y, b2.y) & ABSM; f2fma(ga0, gx, s2.y);
                gx = f2add(a1.x, b2.x) & ABSM; f2fma(ga1, gx, s2.x);
                gx = f2add(a1.y, b2.y) & ABSM; f2fma(ga1, gx, s2.y);
            }
            float xjx = sm[OFF_XS + 2 * jlA];
            float xjy = sm[OFF_XS + 2 * jlA + 1];
            float Bj  = sm[OFF_BT + jlA];
            float2 f0 = f2unpack(ga0), f1 = f2unpack(ga1);
            float G0 = ccA0 + Bj + f0.x + f0.y;
            float G1 = ccA1 + Bj + f1.x + f1.y;
            float p0 = P[(2 * igA) * N_NODES + j0 + jlA];
            float p1 = P[(2 * igA + 1) * N_NODES + j0 + jlA];
            float pg0 = p0 * G0, pg1 = p1 * G1;
            dxx0 = fmaf(pg0, xix0 - xjx, dxx0);
            dxy0 = fmaf(pg0, xiy0 - xjy, dxy0);
            dxx1 = fmaf(pg1, xix1 - xjx, dxx1);
            dxy1 = fmaf(pg1, xiy1 - xjy, dxy1);
        }

        // ---- phase B: agg_h ----
        {
            const float* prow = &P[iB * N_NODES + j0];
#pragma unroll 4
            for (int jc = 0; jc < 16; ++jc) {
                float4 p4 = *(const float4*)&prow[4 * jc];
                const float* vb = &sm[OFF_VT + (4 * jc) * TILE_KT_ROWS + 4 * c4];
                float pv[4] = {p4.x, p4.y, p4.z, p4.w};
#pragma unroll
                for (int r = 0; r < 4; ++r) {
                    ulonglong2 v2 = *(const ulonglong2*)&vb[r * TILE_KT_ROWS];
                    u64 pb = f2pack(pv[r], pv[r]);
                    f2fma(av0, pb, v2.x);
                    f2fma(av1, pb, v2.y);
                }
            }
        }
        __syncthreads();
    }

    // ================= Epilogue =================
    {
        int gi = i0 + iB;
        float2 a = f2unpack(av0), b = f2unpack(av1);
        float4 hv = *(const float4*)&h[gi * H + 4 * c4];
        float4 o;
        o.x = hv.x + a.x; o.y = hv.y + a.y;
        o.z = hv.z + b.x; o.w = hv.w + b.y;
        *(float4*)&out_h[gi * H + 4 * c4] = o;
    }
#pragma unroll
    for (int s = 16; s > 0; s >>= 1) {
        dxx0 += __shfl_xor_sync(0xffffffffu, dxx0, s);
        dxy0 += __shfl_xor_sync(0xffffffffu, dxy0, s);
        dxx1 += __shfl_xor_sync(0xffffffffu, dxx1, s);
        dxy1 += __shfl_xor_sync(0xffffffffu, dxy1, s);
    }
    {
        int w = t >> 5, lane = t & 31;
        if (lane == 0) {
            DXR[w * 4 + 0] = dxx0;
            DXR[w * 4 + 1] = dxy0;
            DXR[w * 4 + 2] = dxx1;
            DXR[w * 4 + 3] = dxy1;
        }
    }
    __syncthreads();
    if (t < 8) {
        int i = t;
        int wg = 2 * (i >> 1);       // first warp of the ig group for row i
        int r = i & 1;
        float ddx = DXR[wg * 4 + r * 2 + 0] + DXR[(wg + 1) * 4 + r * 2 + 0];
        float ddy = DXR[wg * 4 + r * 2 + 1] + DXR[(wg + 1) * 4 + r * 2 + 1];
        int gi = i0 + i;
        out_x[gi * 2]     = x[gi * 2] + ddx;
        out_x[gi * 2 + 1] = x[gi * 2 + 1] + ddy;
    }
}

// ---------------------------------------------------------------------------
extern "C" void kernel_launch(void* const* d_in, const int* in_sizes, int n_in,
                              void* d_out, int out_size)
{
    const float* h   = (const float*)d_in[0];
    const float* x   = (const float*)d_in[1];
    const float* Wq  = (const float*)d_in[3];
    const float* bq  = (const float*)d_in[4];
    const float* Wk  = (const float*)d_in[5];
    const float* bk  = (const float*)d_in[6];
    const float* Wv  = (const float*)d_in[7];
    const float* bv  = (const float*)d_in[8];
    const float* We1 = (const float*)d_in[9];
    const float* be1 = (const float*)d_in[10];
    const float* We2 = (const float*)d_in[11];
    const float* be2 = (const float*)d_in[12];
    const float* Wc  = (const float*)d_in[13];
    const float* bc  = (const float*)d_in[14];

    float* out   = (float*)d_out;
    float* out_h = out;
    float* out_x = out + N_NODES * H;

    size_t smem_bytes = (size_t)SMEM_FLOATS * sizeof(float);
    cudaFuncSetAttribute(main_kernel,
                         cudaFuncAttributeMaxDynamicSharedMemorySize,
                         (int)smem_bytes);

    prep_w_kernel<<<1, 256>>>(We2, be2, Wc, bc);
    prep_node_kernel<<<N_NODES / 8, THREADS>>>(h, x, Wq, bq, Wk, bk, Wv, bv, We1, be1);
    main_kernel<<<N_NODES / BI, THREADS, smem_bytes>>>(h, x, out_h, out_x);
}

// round 3
// speedup vs baseline: 2.5885x; 1.4635x over previous
#include <cuda_runtime.h>
#include <math.h>

#define NN 1024
#define H 128
#define THREADS 256

typedef unsigned long long u64;
#define ABSM 0x7FFFFFFF7FFFFFFFULL

// ---------------- f32x2 packed helpers ----------------
__device__ __forceinline__ u64 f2add(u64 a, u64 b) {
    u64 r; asm("add.rn.f32x2 %0,%1,%2;" : "=l"(r) : "l"(a), "l"(b)); return r;
}
__device__ __forceinline__ void f2fma(u64& d, u64 a, u64 b) {
    asm("fma.rn.f32x2 %0,%1,%2,%0;" : "+l"(d) : "l"(a), "l"(b));
}
__device__ __forceinline__ float2 f2un(u64 v) {
    float2 f; asm("mov.b64 {%0,%1},%2;" : "=f"(f.x), "=f"(f.y) : "l"(v)); return f;
}
__device__ __forceinline__ u64 f2dup(float a) {
    u64 r; asm("mov.b64 %0,{%1,%1};" : "=l"(r) : "f"(a)); return r;
}

// ---------------- device scratch ----------------
__device__ float g_q[NN * H];    // q / sqrt(H), row-major [node][m]
__device__ float g_kT[H * NN];   // k transposed  [m][node]
__device__ float g_v[NN * H];    // v row-major
__device__ float g_al[NN * H];   // alpha = 0.5*w*(u+be1), row-major
__device__ float g_bT[H * NN];   // beta  = -0.5*w*u, transposed [m][node]
__device__ float g_A[NN];        // sum_m alpha
__device__ float g_B[NN];        // sum_m beta
__device__ float g_sig[H];       // sign(w)
__device__ float g_c;            // be2 @ Wc + bc

// ---------------------------------------------------------------------------
// prep: w-fold + qkv GEMV + alpha/beta (+transposes)   128 blocks x 256 thr
// ---------------------------------------------------------------------------
__global__ __launch_bounds__(THREADS)
void prep_kernel(const float* __restrict__ h, const float* __restrict__ x,
                 const float* __restrict__ Wq, const float* __restrict__ bq,
                 const float* __restrict__ Wk, const float* __restrict__ bk,
                 const float* __restrict__ Wv, const float* __restrict__ bv,
                 const float* __restrict__ We1, const float* __restrict__ be1,
                 const float* __restrict__ We2, const float* __restrict__ be2,
                 const float* __restrict__ Wc, const float* __restrict__ bc)
{
    __shared__ float hs[8 * H];
    __shared__ float xs2[8][2];
    __shared__ float ws[H];
    __shared__ float part[128];
    __shared__ float wpart[8][4][2];
    int t = threadIdx.x;
    int r0 = blockIdx.x * 8;

    for (int idx = t; idx < 8 * H; idx += THREADS) hs[idx] = h[r0 * H + idx];
    if (t < 16) xs2[t >> 1][t & 1] = x[r0 * 2 + t];

    // ---- fold: w[m] = We2[m,:]@Wc ; sig ; c ----
    {
        int m = t >> 1, half = t & 1;
        const float* row = We2 + m * H + half * 64;
        const float* wc  = Wc + half * 64;
        float acc = 0.f;
#pragma unroll 16
        for (int o = 0; o < 64; ++o) acc = fmaf(row[o], wc[o], acc);
        acc += __shfl_xor_sync(0xffffffffu, acc, 1);
        if (!half) {
            ws[m] = acc;
            if (r0 == 0) g_sig[m] = (acc >= 0.f) ? 1.0f : -1.0f;
        }
    }
    if (t < 128) part[t] = be2[t] * Wc[t];
    __syncthreads();
    for (int s = 64; s > 0; s >>= 1) {
        if (t < s) part[t] += part[t + s];
        __syncthreads();
    }
    if (t == 0 && r0 == 0) g_c = part[0] + bc[0];

    // ---- qkv GEMV ----
    int o = t & 127;
    int g = t >> 7;
    const float SCALE = 0.08838834764831845f;  // 1/sqrt(128)

    float aq[4], ak[4], av[4];
    float bqv = bq[o], bkv = bk[o], bvv = bv[o];
#pragma unroll
    for (int r = 0; r < 4; ++r) { aq[r] = bqv; ak[r] = bkv; av[r] = bvv; }

#pragma unroll 4
    for (int m = 0; m < H; ++m) {
        float wq = Wq[m * H + o];
        float wk = Wk[m * H + o];
        float wv = Wv[m * H + o];
#pragma unroll
        for (int r = 0; r < 4; ++r) {
            float hm = hs[(g * 4 + r) * H + m];
            aq[r] = fmaf(hm, wq, aq[r]);
            ak[r] = fmaf(hm, wk, ak[r]);
            av[r] = fmaf(hm, wv, av[r]);
        }
    }
#pragma unroll
    for (int r = 0; r < 4; ++r) {
        int row = r0 + g * 4 + r;
        g_q[row * H + o] = aq[r] * SCALE;
        g_kT[o * NN + row] = ak[r];          // transposed
        g_v[row * H + o] = av[r];
    }

    // ---- alpha/beta + row sums ----
    float w0 = We1[o], w1 = We1[H + o], b1 = be1[o], wo = ws[o];
    float sA[4], sB[4];
#pragma unroll
    for (int r = 0; r < 4; ++r) {
        int row = r0 + g * 4 + r;
        float u  = fmaf(xs2[g * 4 + r][0], w0, xs2[g * 4 + r][1] * w1);
        float ub = u + b1;
        float al = 0.5f * wo * ub;
        float be = -0.5f * wo * u;
        g_al[row * H + o] = al;
        g_bT[o * NN + row] = be;             // transposed
        sA[r] = al; sB[r] = be;
    }
#pragma unroll
    for (int s = 16; s > 0; s >>= 1) {
#pragma unroll
        for (int r = 0; r < 4; ++r) {
            sA[r] += __shfl_xor_sync(0xffffffffu, sA[r], s);
            sB[r] += __shfl_xor_sync(0xffffffffu, sB[r], s);
        }
    }
    int wr = t >> 5, lane = t & 31;
    if (lane == 0) {
#pragma unroll
        for (int r = 0; r < 4; ++r) { wpart[wr][r][0] = sA[r]; wpart[wr][r][1] = sB[r]; }
    }
    __syncthreads();
    if (t < 8) {
        int gg = t >> 2, rr = t & 3;
        float A = 0.f, B = 0.f;
#pragma unroll
        for (int ww = 0; ww < 4; ++ww) {
            A += wpart[4 * gg + ww][rr][0];
            B += wpart[4 * gg + ww][rr][1];
        }
        int row = r0 + gg * 4 + rr;
        g_A[row] = A;
        g_B[row] = B;
    }
}

// ---------------------------------------------------------------------------
// main: each thread owns ALL 8 i-rows and 4 consecutive j's; warps split j.
// All big operands streamed from L2 via coalesced LDG — no tile staging.
// smem float offsets
// ---------------------------------------------------------------------------
#define SM_QD   0        // 128*16 dup-packed q  [m][i]{dup}
#define SM_AD   2048     // 128*16 dup-packed alpha
#define SM_SD   4096     // 128*2 dup sig
#define SM_XI   4352     // 16
#define SM_ASH  4368     // 8   (c + A_i)
#define SM_DXS  4376     // 128
#define SM_P    4504     // 1024*12 scores [j][i] (stride 12); reused for AV partials
#define SMEM_FLOATS (SM_P + 12288)

__global__ __launch_bounds__(THREADS)
void main_kernel(const float* __restrict__ h, const float* __restrict__ x,
                 float* __restrict__ out_h, float* __restrict__ out_x)
{
    extern __shared__ float sm[];
    float* Qd  = sm + SM_QD;
    float* Ad  = sm + SM_AD;
    float* Sd  = sm + SM_SD;
    float* XI  = sm + SM_XI;
    float* ASH = sm + SM_ASH;
    float* DXS = sm + SM_DXS;
    float* P   = sm + SM_P;

    int t = threadIdx.x;
    int i0 = blockIdx.x * 8;
    int w = t >> 5, l = t & 31;
    int jb = (w << 7) | (l << 2);   // 4 consecutive j owned by this thread

    for (int idx = t; idx < 1024; idx += THREADS) {
        int i = idx & 7, m = idx >> 3;
        float q = g_q[(i0 + i) * H + m];
        Qd[m * 16 + 2 * i] = q; Qd[m * 16 + 2 * i + 1] = q;
        float a = g_al[(i0 + i) * H + m];
        Ad[m * 16 + 2 * i] = a; Ad[m * 16 + 2 * i + 1] = a;
    }
    if (t < H) { float s = g_sig[t]; Sd[2 * t] = s; Sd[2 * t + 1] = s; }
    if (t < 16) XI[t] = x[i0 * 2 + t];
    if (t < 8)  ASH[t] = g_c + g_A[i0 + t];
    __syncthreads();

    // ================= Pass 1: scores =================
    {
        u64 acc[8][2];
#pragma unroll
        for (int i = 0; i < 8; ++i) { acc[i][0] = 0ull; acc[i][1] = 0ull; }
#pragma unroll 4
        for (int m = 0; m < H; ++m) {
            ulonglong2 k2 = *(const ulonglong2*)(g_kT + m * NN + jb);
            const u64* qp = (const u64*)(Qd + m * 16);
#pragma unroll
            for (int i = 0; i < 8; ++i) {
                u64 qd = qp[i];
                f2fma(acc[i][0], qd, k2.x);
                f2fma(acc[i][1], qd, k2.y);
            }
        }
#pragma unroll
        for (int jj = 0; jj < 4; ++jj) {
            float s[8];
#pragma unroll
            for (int i = 0; i < 8; ++i) {
                float2 f = f2un(acc[i][jj >> 1]);
                s[i] = (jj & 1) ? f.y : f.x;
            }
            float4* dst = (float4*)&P[(jb + jj) * 12];
            dst[0] = make_float4(s[0], s[1], s[2], s[3]);
            dst[1] = make_float4(s[4], s[5], s[6], s[7]);
        }
    }
    __syncthreads();

    // ================= Softmax: warp w owns row w =================
    {
        float mx = -1e30f;
        for (int j = l; j < NN; j += 32) mx = fmaxf(mx, P[j * 12 + w]);
#pragma unroll
        for (int s = 16; s > 0; s >>= 1)
            mx = fmaxf(mx, __shfl_xor_sync(0xffffffffu, mx, s));
        float sum = 0.f;
        for (int j = l; j < NN; j += 32) {
            float e = __expf(P[j * 12 + w] - mx);
            P[j * 12 + w] = e;
            sum += e;
        }
#pragma unroll
        for (int s = 16; s > 0; s >>= 1)
            sum += __shfl_xor_sync(0xffffffffu, sum, s);
        float inv = 1.f / sum;
        for (int j = l; j < NN; j += 32) P[j * 12 + w] *= inv;
    }
    __syncthreads();

    // ================= Gate + delta_x =================
    {
        u64 ga[8][2];
#pragma unroll
        for (int i = 0; i < 8; ++i) { ga[i][0] = 0ull; ga[i][1] = 0ull; }
#pragma unroll 4
        for (int m = 0; m < H; ++m) {
            ulonglong2 b2 = *(const ulonglong2*)(g_bT + m * NN + jb);
            u64 sd = *(const u64*)(Sd + 2 * m);
            const u64* ap = (const u64*)(Ad + m * 16);
#pragma unroll
            for (int i = 0; i < 8; ++i) {
                u64 ai = ap[i];
                u64 z0 = f2add(ai, b2.x) & ABSM;
                u64 z1 = f2add(ai, b2.y) & ABSM;
                f2fma(ga[i][0], z0, sd);
                f2fma(ga[i][1], z1, sd);
            }
        }
        float4 B4  = *(const float4*)(g_B + jb);
        float4 xq0 = *(const float4*)(x + jb * 2);
        float4 xq1 = *(const float4*)(x + jb * 2 + 4);
        float Bv[4]  = {B4.x, B4.y, B4.z, B4.w};
        float xjx[4] = {xq0.x, xq0.z, xq1.x, xq1.z};
        float xjy[4] = {xq0.y, xq0.w, xq1.y, xq1.w};
        float dxv[8], dyv[8];
#pragma unroll
        for (int i = 0; i < 8; ++i) { dxv[i] = 0.f; dyv[i] = 0.f; }
#pragma unroll
        for (int jj = 0; jj < 4; ++jj) {
#pragma unroll
            for (int i = 0; i < 8; ++i) {
                float2 f = f2un(ga[i][jj >> 1]);
                float gv = (jj & 1) ? f.y : f.x;
                float G = ASH[i] + Bv[jj] + gv;
                float p = P[(jb + jj) * 12 + i];
                float pg = p * G;
                dxv[i] = fmaf(pg, XI[2 * i]     - xjx[jj], dxv[i]);
                dyv[i] = fmaf(pg, XI[2 * i + 1] - xjy[jj], dyv[i]);
            }
        }
#pragma unroll
        for (int s = 16; s > 0; s >>= 1) {
#pragma unroll
            for (int i = 0; i < 8; ++i) {
                dxv[i] += __shfl_xor_sync(0xffffffffu, dxv[i], s);
                dyv[i] += __shfl_xor_sync(0xffffffffu, dyv[i], s);
            }
        }
        if (l == 0) {
#pragma unroll
            for (int i = 0; i < 8; ++i) {
                DXS[w * 16 + 2 * i]     = dxv[i];
                DXS[w * 16 + 2 * i + 1] = dyv[i];
            }
        }
    }

    // ================= AV: warp sweeps its 128 j, lane owns 4 cols ========
    u64 av[8][2];
#pragma unroll
    for (int i = 0; i < 8; ++i) { av[i][0] = 0ull; av[i][1] = 0ull; }
    int c0 = l << 2;
    {
        int jbase = w << 7;
#pragma unroll 2
        for (int jj = 0; jj < 128; ++jj) {
            int j = jbase + jj;
            ulonglong2 v2 = *(const ulonglong2*)(g_v + j * H + c0);
            const float* pr = &P[j * 12];
#pragma unroll
            for (int i = 0; i < 8; ++i) {
                u64 pd = f2dup(pr[i]);
                f2fma(av[i][0], pd, v2.x);
                f2fma(av[i][1], pd, v2.y);
            }
        }
    }
    __syncthreads();       // all warps done reading P
    // overlay AV partials into P region: RED[w][i][c]
#pragma unroll
    for (int i = 0; i < 8; ++i) {
        float2 a = f2un(av[i][0]);
        float2 b = f2un(av[i][1]);
        *(float4*)&P[(w * 8 + i) * 128 + c0] = make_float4(a.x, a.y, b.x, b.y);
    }
    __syncthreads();

    // ================= Final reduce + epilogue =================
    {
        int i = t >> 5, c = (t & 31) << 2;
        float4 s0 = make_float4(0.f, 0.f, 0.f, 0.f);
#pragma unroll
        for (int w2 = 0; w2 < 8; ++w2) {
            float4 r = *(float4*)&P[(w2 * 8 + i) * 128 + c];
            s0.x += r.x; s0.y += r.y; s0.z += r.z; s0.w += r.w;
        }
        float4 hv = *(const float4*)(h + (i0 + i) * H + c);
        *(float4*)(out_h + (i0 + i) * H + c) =
            make_float4(hv.x + s0.x, hv.y + s0.y, hv.z + s0.z, hv.w + s0.w);
    }
    if (t < 16) {
        int i = t >> 1, d = t & 1;
        float s = 0.f;
#pragma unroll
        for (int w2 = 0; w2 < 8; ++w2) s += DXS[w2 * 16 + 2 * i + d];
        out_x[(i0 + i) * 2 + d] = x[(i0 + i) * 2 + d] + s;
    }
}

// ---------------------------------------------------------------------------
extern "C" void kernel_launch(void* const* d_in, const int* in_sizes, int n_in,
                              void* d_out, int out_size)
{
    const float* h   = (const float*)d_in[0];
    const float* x   = (const float*)d_in[1];
    const float* Wq  = (const float*)d_in[3];
    const float* bq  = (const float*)d_in[4];
    const float* Wk  = (const float*)d_in[5];
    const float* bk  = (const float*)d_in[6];
    const float* Wv  = (const float*)d_in[7];
    const float* bv  = (const float*)d_in[8];
    const float* We1 = (const float*)d_in[9];
    const float* be1 = (const float*)d_in[10];
    const float* We2 = (const float*)d_in[11];
    const float* be2 = (const float*)d_in[12];
    const float* Wc  = (const float*)d_in[13];
    const float* bc  = (const float*)d_in[14];

    float* out   = (float*)d_out;
    float* out_h = out;
    float* out_x = out + NN * H;

    size_t smem_bytes = (size_t)SMEM_FLOATS * sizeof(float);
    cudaFuncSetAttribute(main_kernel,
                         cudaFuncAttributeMaxDynamicSharedMemorySize,
                         (int)smem_bytes);

    prep_kernel<<<NN / 8, THREADS>>>(h, x, Wq, bq, Wk, bk, Wv, bv,
                                     We1, be1, We2, be2, Wc, bc);
    main_kernel<<<NN / 8, THREADS, smem_bytes>>>(h, x, out_h, out_x);
}

// round 4
// speedup vs baseline: 3.1131x; 1.2027x over previous
#include <cuda_runtime.h>
#include <math.h>

#define NN 1024
#define H 128
#define THREADS 512     // main kernel
#define PTHREADS 256    // prep kernel

typedef unsigned long long u64;
#define ABSM 0x7FFFFFFF7FFFFFFFULL

// ---------------- f32x2 packed helpers ----------------
__device__ __forceinline__ u64 f2add(u64 a, u64 b) {
    u64 r; asm("add.rn.f32x2 %0,%1,%2;" : "=l"(r) : "l"(a), "l"(b)); return r;
}
__device__ __forceinline__ void f2fma(u64& d, u64 a, u64 b) {
    asm("fma.rn.f32x2 %0,%1,%2,%0;" : "+l"(d) : "l"(a), "l"(b));
}
__device__ __forceinline__ float2 f2un(u64 v) {
    float2 f; asm("mov.b64 {%0,%1},%2;" : "=f"(f.x), "=f"(f.y) : "l"(v)); return f;
}
__device__ __forceinline__ u64 f2dup(float a) {
    u64 r; asm("mov.b64 %0,{%1,%1};" : "=l"(r) : "f"(a)); return r;
}

// ---------------- device scratch ----------------
__device__ float g_q[NN * H];    // q / sqrt(H), row-major [node][m]
__device__ float g_kT[H * NN];   // k transposed  [m][node]
__device__ float g_v[NN * H];    // v row-major
__device__ float g_al[NN * H];   // alpha = 0.5*w*(u+be1), row-major
__device__ float g_bT[H * NN];   // beta  = -0.5*w*u, transposed [m][node]
__device__ float g_A[NN];
__device__ float g_B[NN];
__device__ float g_sig[H];
__device__ float g_c;

// ---------------------------------------------------------------------------
// prep: w-fold + qkv GEMV + alpha/beta (+transposes)   128 blocks x 256 thr
// ---------------------------------------------------------------------------
__global__ __launch_bounds__(PTHREADS)
void prep_kernel(const float* __restrict__ h, const float* __restrict__ x,
                 const float* __restrict__ Wq, const float* __restrict__ bq,
                 const float* __restrict__ Wk, const float* __restrict__ bk,
                 const float* __restrict__ Wv, const float* __restrict__ bv,
                 const float* __restrict__ We1, const float* __restrict__ be1,
                 const float* __restrict__ We2, const float* __restrict__ be2,
                 const float* __restrict__ Wc, const float* __restrict__ bc)
{
    __shared__ float hs[8 * H];
    __shared__ float xs2[8][2];
    __shared__ float ws[H];
    __shared__ float part[128];
    __shared__ float wpart[8][4][2];
    int t = threadIdx.x;
    int r0 = blockIdx.x * 8;

    for (int idx = t; idx < 8 * H; idx += PTHREADS) hs[idx] = h[r0 * H + idx];
    if (t < 16) xs2[t >> 1][t & 1] = x[r0 * 2 + t];

    {
        int m = t >> 1, half = t & 1;
        const float* row = We2 + m * H + half * 64;
        const float* wc  = Wc + half * 64;
        float acc = 0.f;
#pragma unroll 16
        for (int o = 0; o < 64; ++o) acc = fmaf(row[o], wc[o], acc);
        acc += __shfl_xor_sync(0xffffffffu, acc, 1);
        if (!half) {
            ws[m] = acc;
            if (r0 == 0) g_sig[m] = (acc >= 0.f) ? 1.0f : -1.0f;
        }
    }
    if (t < 128) part[t] = be2[t] * Wc[t];
    __syncthreads();
    for (int s = 64; s > 0; s >>= 1) {
        if (t < s) part[t] += part[t + s];
        __syncthreads();
    }
    if (t == 0 && r0 == 0) g_c = part[0] + bc[0];

    int o = t & 127;
    int g = t >> 7;
    const float SCALE = 0.08838834764831845f;

    float aq[4], ak[4], av[4];
    float bqv = bq[o], bkv = bk[o], bvv = bv[o];
#pragma unroll
    for (int r = 0; r < 4; ++r) { aq[r] = bqv; ak[r] = bkv; av[r] = bvv; }

#pragma unroll 4
    for (int m = 0; m < H; ++m) {
        float wq = Wq[m * H + o];
        float wk = Wk[m * H + o];
        float wv = Wv[m * H + o];
#pragma unroll
        for (int r = 0; r < 4; ++r) {
            float hm = hs[(g * 4 + r) * H + m];
            aq[r] = fmaf(hm, wq, aq[r]);
            ak[r] = fmaf(hm, wk, ak[r]);
            av[r] = fmaf(hm, wv, av[r]);
        }
    }
#pragma unroll
    for (int r = 0; r < 4; ++r) {
        int row = r0 + g * 4 + r;
        g_q[row * H + o] = aq[r] * SCALE;
        g_kT[o * NN + row] = ak[r];
        g_v[row * H + o] = av[r];
    }

    float w0 = We1[o], w1 = We1[H + o], b1 = be1[o], wo = ws[o];
    float sA[4], sB[4];
#pragma unroll
    for (int r = 0; r < 4; ++r) {
        int row = r0 + g * 4 + r;
        float u  = fmaf(xs2[g * 4 + r][0], w0, xs2[g * 4 + r][1] * w1);
        float ub = u + b1;
        float al = 0.5f * wo * ub;
        float be = -0.5f * wo * u;
        g_al[row * H + o] = al;
        g_bT[o * NN + row] = be;
        sA[r] = al; sB[r] = be;
    }
#pragma unroll
    for (int s = 16; s > 0; s >>= 1) {
#pragma unroll
        for (int r = 0; r < 4; ++r) {
            sA[r] += __shfl_xor_sync(0xffffffffu, sA[r], s);
            sB[r] += __shfl_xor_sync(0xffffffffu, sB[r], s);
        }
    }
    int wr = t >> 5, lane = t & 31;
    if (lane == 0) {
#pragma unroll
        for (int r = 0; r < 4; ++r) { wpart[wr][r][0] = sA[r]; wpart[wr][r][1] = sB[r]; }
    }
    __syncthreads();
    if (t < 8) {
        int gg = t >> 2, rr = t & 3;
        float A = 0.f, B = 0.f;
#pragma unroll
        for (int ww = 0; ww < 4; ++ww) {
            A += wpart[4 * gg + ww][rr][0];
            B += wpart[4 * gg + ww][rr][1];
        }
        int row = r0 + gg * 4 + rr;
        g_A[row] = A;
        g_B[row] = B;
    }
}

// ---------------------------------------------------------------------------
// main: 128 blocks x 512 threads (16 warps). Thread owns 2 j's, all 8 i.
// ---------------------------------------------------------------------------
#define SM_QD   0        // 128*16 dup-packed q [m][i-dup]
#define SM_AD   2048     // 128*16 dup-packed alpha
#define SM_SD   4096     // 128*2 dup sig
#define SM_XI   4352     // 16
#define SM_ASH  4368     // 8
#define SM_SMX  4376     // 16
#define SM_SSUM 4392     // 16
#define SM_DXS  4408     // 16*16
#define SM_P    4664     // 8*1024 scores [i][j]
#define SM_AVP  12856    // 16*8*128 AV partials
#define SMEM_FLOATS (SM_AVP + 16384)

__global__ __launch_bounds__(THREADS)
void main_kernel(const float* __restrict__ h, const float* __restrict__ x,
                 float* __restrict__ out_h, float* __restrict__ out_x)
{
    extern __shared__ float sm[];
    float* Qd  = sm + SM_QD;
    float* Ad  = sm + SM_AD;
    float* Sd  = sm + SM_SD;
    float* XI  = sm + SM_XI;
    float* ASH = sm + SM_ASH;
    float* SMX = sm + SM_SMX;
    float* SSUM= sm + SM_SSUM;
    float* DXS = sm + SM_DXS;
    float* P   = sm + SM_P;
    float* AVP = sm + SM_AVP;

    int t = threadIdx.x;
    int i0 = blockIdx.x * 8;
    int w = t >> 5, l = t & 31;
    int jb = (w << 6) | (l << 1);    // 2 consecutive j's

    for (int idx = t; idx < 1024; idx += THREADS) {
        int i = idx & 7, m = idx >> 3;
        float q = g_q[(i0 + i) * H + m];
        Qd[m * 16 + 2 * i] = q; Qd[m * 16 + 2 * i + 1] = q;
        float a = g_al[(i0 + i) * H + m];
        Ad[m * 16 + 2 * i] = a; Ad[m * 16 + 2 * i + 1] = a;
    }
    if (t < H) { float s = g_sig[t]; Sd[2 * t] = s; Sd[2 * t + 1] = s; }
    if (t < 16) XI[t] = x[i0 * 2 + t];
    if (t < 8)  ASH[t] = g_c + g_A[i0 + t];
    __syncthreads();

    // ============ Fused score + gate m-loop ============
    u64 acc[8], ga[8];
#pragma unroll
    for (int i = 0; i < 8; ++i) { acc[i] = 0ull; ga[i] = 0ull; }
#pragma unroll 4
    for (int m = 0; m < H; ++m) {
        u64 k2 = *(const u64*)(g_kT + m * NN + jb);
        u64 b2 = *(const u64*)(g_bT + m * NN + jb);
        u64 sd = *(const u64*)(Sd + 2 * m);
        const ulonglong2* qp = (const ulonglong2*)(Qd + m * 16);
        const ulonglong2* ap = (const ulonglong2*)(Ad + m * 16);
#pragma unroll
        for (int i2 = 0; i2 < 4; ++i2) {
            ulonglong2 q2 = qp[i2];
            ulonglong2 a2 = ap[i2];
            f2fma(acc[2 * i2],     q2.x, k2);
            f2fma(acc[2 * i2 + 1], q2.y, k2);
            u64 z0 = f2add(a2.x, b2) & ABSM;
            u64 z1 = f2add(a2.y, b2) & ABSM;
            f2fma(ga[2 * i2],     z0, sd);
            f2fma(ga[2 * i2 + 1], z1, sd);
        }
    }
#pragma unroll
    for (int i = 0; i < 8; ++i) {
        float2 f = f2un(acc[i]);
        *(float2*)&P[i * NN + jb] = f;
    }
    __syncthreads();

    // ============ Softmax: 2 warps per row (j-halves) ============
    {
        int row = w & 7, half = w >> 3;
        float* prow = P + row * NN + half * 512;
        float mx = -1e30f;
        for (int j = l; j < 512; j += 32) mx = fmaxf(mx, prow[j]);
#pragma unroll
        for (int s = 16; s > 0; s >>= 1)
            mx = fmaxf(mx, __shfl_xor_sync(0xffffffffu, mx, s));
        if (l == 0) SMX[w] = mx;
        __syncthreads();
        float M = fmaxf(SMX[row], SMX[row + 8]);
        float sum = 0.f;
        for (int j = l; j < 512; j += 32) {
            float e = __expf(prow[j] - M);
            prow[j] = e;
            sum += e;
        }
#pragma unroll
        for (int s = 16; s > 0; s >>= 1)
            sum += __shfl_xor_sync(0xffffffffu, sum, s);
        if (l == 0) SSUM[w] = sum;
        __syncthreads();
        float inv = 1.f / (SSUM[row] + SSUM[row + 8]);
        for (int j = l; j < 512; j += 32) prow[j] *= inv;
    }
    __syncthreads();

    // ============ Gate combine: delta_x ============
    {
        float2 B2 = *(const float2*)(g_B + jb);
        float4 xj = *(const float4*)(x + jb * 2);   // (xj0,yj0,xj1,yj1)
        float dxv[8], dyv[8];
#pragma unroll
        for (int i = 0; i < 8; ++i) {
            float2 g2 = f2un(ga[i]);
            float G0 = ASH[i] + B2.x + g2.x;
            float G1 = ASH[i] + B2.y + g2.y;
            float2 p = *(float2*)&P[i * NN + jb];
            float pg0 = p.x * G0, pg1 = p.y * G1;
            float xi = XI[2 * i], yi = XI[2 * i + 1];
            dxv[i] = fmaf(pg0, xi - xj.x, pg1 * (xi - xj.z));
            dyv[i] = fmaf(pg0, yi - xj.y, pg1 * (yi - xj.w));
        }
#pragma unroll
        for (int s = 16; s > 0; s >>= 1) {
#pragma unroll
            for (int i = 0; i < 8; ++i) {
                dxv[i] += __shfl_xor_sync(0xffffffffu, dxv[i], s);
                dyv[i] += __shfl_xor_sync(0xffffffffu, dyv[i], s);
            }
        }
        if (l == 0) {
#pragma unroll
            for (int i = 0; i < 8; ++i) {
                DXS[w * 16 + 2 * i]     = dxv[i];
                DXS[w * 16 + 2 * i + 1] = dyv[i];
            }
        }
    }

    // ============ AV: warp sweeps 64 j, lane owns 4 cols ============
    {
        u64 av[8][2];
#pragma unroll
        for (int i = 0; i < 8; ++i) { av[i][0] = 0ull; av[i][1] = 0ull; }
        int c0 = l << 2;
        int jbase = w << 6;
#pragma unroll 2
        for (int jj = 0; jj < 64; ++jj) {
            int j = jbase + jj;
            ulonglong2 v2 = *(const ulonglong2*)(g_v + j * H + c0);
#pragma unroll
            for (int i = 0; i < 8; ++i) {
                u64 pd = f2dup(P[i * NN + j]);    // warp-uniform broadcast
                f2fma(av[i][0], pd, v2.x);
                f2fma(av[i][1], pd, v2.y);
            }
        }
#pragma unroll
        for (int i = 0; i < 8; ++i) {
            float2 a = f2un(av[i][0]);
            float2 b = f2un(av[i][1]);
            *(float4*)&AVP[(w * 8 + i) * 128 + c0] = make_float4(a.x, a.y, b.x, b.y);
        }
    }
    __syncthreads();

    // ============ Final reduce + epilogue ============
    {
        int i = t >> 6;
        int c = (t & 63) * 2;
        float2 s = make_float2(0.f, 0.f);
#pragma unroll
        for (int w2 = 0; w2 < 16; ++w2) {
            float2 r = *(float2*)&AVP[(w2 * 8 + i) * 128 + c];
            s.x += r.x; s.y += r.y;
        }
        float2 hv = *(const float2*)(h + (i0 + i) * H + c);
        *(float2*)(out_h + (i0 + i) * H + c) = make_float2(hv.x + s.x, hv.y + s.y);
    }
    if (t < 16) {
        int i = t >> 1, d = t & 1;
        float s = 0.f;
#pragma unroll
        for (int w2 = 0; w2 < 16; ++w2) s += DXS[w2 * 16 + 2 * i + d];
        out_x[(i0 + i) * 2 + d] = x[(i0 + i) * 2 + d] + s;
    }
}

// ---------------------------------------------------------------------------
extern "C" void kernel_launch(void* const* d_in, const int* in_sizes, int n_in,
                              void* d_out, int out_size)
{
    const float* h   = (const float*)d_in[0];
    const float* x   = (const float*)d_in[1];
    const float* Wq  = (const float*)d_in[3];
    const float* bq  = (const float*)d_in[4];
    const float* Wk  = (const float*)d_in[5];
    const float* bk  = (const float*)d_in[6];
    const float* Wv  = (const float*)d_in[7];
    const float* bv  = (const float*)d_in[8];
    const float* We1 = (const float*)d_in[9];
    const float* be1 = (const float*)d_in[10];
    const float* We2 = (const float*)d_in[11];
    const float* be2 = (const float*)d_in[12];
    const float* Wc  = (const float*)d_in[13];
    const float* bc  = (const float*)d_in[14];

    float* out   = (float*)d_out;
    float* out_h = out;
    float* out_x = out + NN * H;

    size_t smem_bytes = (size_t)SMEM_FLOATS * sizeof(float);
    cudaFuncSetAttribute(main_kernel,
                         cudaFuncAttributeMaxDynamicSharedMemorySize,
                         (int)smem_bytes);

    prep_kernel<<<NN / 8, PTHREADS>>>(h, x, Wq, bq, Wk, bk, Wv, bv,
                                      We1, be1, We2, be2, Wc, bc);
    main_kernel<<<NN / 8, THREADS, smem_bytes>>>(h, x, out_h, out_x);
}